// round 13
// baseline (speedup 1.0000x reference)
#include <cuda_runtime.h>
#include <cuda_bf16.h>

// x: [32, 512, 512, 3] f32  -> out: [32, 128, 128, 3] f32
// 13-tap separable gaussian (sigma=1.5), zero padding, out = blur[4i, 4j]
//
// R12 structure (16 rows/CTA as four 4-row groups, ping-pong planar smem,
// horizontal pass interleaved into next group's vertical loop, cache-policy
// segregation) + PACKED f32x2 FMA in phase 1 (fma.rn.f32x2, sm_10x-only,
// inline PTX): 52 scalar FFMA -> 26 FFMA2 per 512B load, raising
// bytes-per-issue-slot ~1.8x. Weights: 7 packed b64 regs (w[k]=w[12-k]).

#define ROWF4   384              // float4 per input image row (512*3/4)
#define PROW    528              // floats per padded plane row (8 + 512 + 8)
#define GROWS   4                // output rows per group
#define NGROUP  4                // groups per CTA -> 16 output rows
#define GPLANE  (GROWS * PROW)   // floats per plane per group    = 2112
#define GBUF    (3 * GPLANE)     // floats per group buffer       = 6336
#define SMEM_BYTES (2 * GBUF * 4)   // 50688 B (ping-pong)

#define GNIN    (4 * GROWS + 9)  // input rows per group          = 25
#define PF      6                // ring depth; PF>=6 -> R0+s+PF >= 0 always

typedef unsigned long long u64;

__device__ __forceinline__ u64 fma2(u64 a, u64 b, u64 c) {
    u64 d;
    asm("fma.rn.f32x2 %0, %1, %2, %3;" : "=l"(d) : "l"(a), "l"(b), "l"(c));
    return d;
}
__device__ __forceinline__ u64 pack2(float x) {
    u64 r;
    asm("mov.b64 %0, {%1, %1};" : "=l"(r) : "f"(x));
    return r;
}
__device__ __forceinline__ ulonglong2 u2zero() { return make_ulonglong2(0ull, 0ull); }

// one horizontal output row rr from a group buffer (scalar, FFMA-imm)
__device__ __forceinline__ void phase2_row(
    const float* __restrict__ smbuf, int rr, int j, int c,
    float* __restrict__ opix, const float* __restrict__ Wt)
{
    const float4* sp4 = reinterpret_cast<const float4*>(smbuf)
                      + c * (GPLANE / 4) + rr * (PROW / 4) + j;
    float4 a = sp4[0];
    float4 b = sp4[1];
    float4 d = sp4[2];
    float4 e = sp4[3];
    // s[0..15] = cols 4j-8 .. 4j+7 ; taps at s[2..14]
    float acch;
    acch = Wt[0] * a.z;
    acch = fmaf(Wt[1],  a.w, acch);
    acch = fmaf(Wt[2],  b.x, acch);
    acch = fmaf(Wt[3],  b.y, acch);
    acch = fmaf(Wt[4],  b.z, acch);
    acch = fmaf(Wt[5],  b.w, acch);
    acch = fmaf(Wt[6],  d.x, acch);
    acch = fmaf(Wt[7],  d.y, acch);
    acch = fmaf(Wt[8],  d.z, acch);
    acch = fmaf(Wt[9],  d.w, acch);
    acch = fmaf(Wt[10], e.x, acch);
    acch = fmaf(Wt[11], e.y, acch);
    acch = fmaf(Wt[12], e.z, acch);
    __stcs(&opix[rr * 384], acch);           // streaming store (never re-read)
}

// vertical streaming pass (packed f32x2) for one 4-row group; if P2BUF is
// non-null, one phase-2 row of the OTHER buffer is interleaved at s=5,11,17,23.
__device__ __forceinline__ void phase1_group(
    const ulonglong2* __restrict__ xcol, int R0,
    float* __restrict__ smbuf, const int* __restrict__ sbase,
    const u64* __restrict__ w2, const float* __restrict__ Wt,
    const float* __restrict__ P2BUF, int j, int c, float* __restrict__ opix)
{
    ulonglong2 buf[PF];
    #pragma unroll
    for (int s = 0; s < PF; ++s) {               // preload rows R0 .. R0+5
        int r = R0 + s;                          // boundary rows: allocate in L2
        buf[s] = (r >= 0) ? __ldg(xcol + r * ROWF4) : u2zero();
    }

    ulonglong2 acc[GROWS];
    #pragma unroll
    for (int q = 0; q < GROWS; ++q) acc[q] = u2zero();

    #pragma unroll
    for (int s = 0; s < GNIN; ++s) {
        const ulonglong2 v = buf[s % PF];

        if (s + PF < GNIN) {                     // refill; R0+s+PF >= 0 (PF>=6)
            const int sr = s + PF;               // row index within group: 6..24
            int r = R0 + sr;
            if (r < 512) {
                if (sr >= GNIN - 9) {
                    buf[s % PF] = __ldg(xcol + r * ROWF4);   // re-read: allocate
                } else {
                    buf[s % PF] = __ldcs(xcol + r * ROWF4);  // read-once: evict-first
                }
            } else {
                buf[s % PF] = u2zero();
            }
        }

        const int p = s & 3;
        #pragma unroll
        for (int k = p; k <= 12; k += 4) {       // taps congruent to s mod 4
            const int ii = (s - k) >> 2;
            if (ii >= 0 && ii < GROWS) {
                const int kk = (k <= 6) ? k : 12 - k;   // symmetric weights
                acc[ii].x = fma2(w2[kk], v.x, acc[ii].x);
                acc[ii].y = fma2(w2[kk], v.y, acc[ii].y);
            }
        }

        // output row ii completes at s = 4*ii + 12 -> unpack + flush (4x STS.32)
        if (s >= 12 && ((s - 12) & 3) == 0) {
            const int ii = (s - 12) >> 2;
            const int ro = ii * PROW;
            float f0, f1, f2, f3;
            asm("mov.b64 {%0, %1}, %2;" : "=f"(f0), "=f"(f1) : "l"(acc[ii].x));
            asm("mov.b64 {%0, %1}, %2;" : "=f"(f2), "=f"(f3) : "l"(acc[ii].y));
            smbuf[sbase[0] + ro] = f0;
            smbuf[sbase[1] + ro] = f1;
            smbuf[sbase[2] + ro] = f2;
            smbuf[sbase[3] + ro] = f3;
            acc[ii] = u2zero();
        }

        // interleaved horizontal row of the previous group's buffer
        if (P2BUF != nullptr && (s == 5 || s == 11 || s == 17 || s == 23)) {
            phase2_row(P2BUF, (s - 5) / 6, j, c, opix, Wt);
        }
    }
}

__global__ __launch_bounds__(384, 2)
void aa_fused(const float4* __restrict__ x4, float* __restrict__ out)
{
    extern __shared__ float sm[];

    const int t  = threadIdx.x;          // 0..383
    const int n  = blockIdx.y;           // image
    const int i0 = blockIdx.x * 16;      // first output row of this CTA

    // normalized 1-D gaussian (sigma = 1.5) as literals
    const float Wt[13] = {
        0.00008922f, 0.00102822f, 0.00759740f, 0.03599436f,
        0.10934121f, 0.21296756f, 0.26596430f, 0.21296756f,
        0.10934121f, 0.03599436f, 0.00759740f, 0.00102822f,
        0.00008922f
    };

    // packed duplicate weights for f32x2 FMA (symmetric: only 7 distinct)
    u64 w2[7];
    #pragma unroll
    for (int k = 0; k < 7; ++k) w2[k] = pack2(Wt[k]);

    // Zero horizontal padding of BOTH buffers:
    // 2 bufs * 3 planes * 4 rows * 16 pad floats = 384 = blockDim
    {
        int bufi  = t / 192;             // 0..1
        int rem   = t - bufi * 192;      // 0..191
        int plane = rem >> 6;            // 0..2
        int rem2  = rem & 63;
        int row   = rem2 >> 4;           // 0..3
        int o     = rem2 & 15;           // 0..15
        sm[bufi * GBUF + plane * GPLANE + row * PROW + (o < 8 ? o : 512 + o)] = 0.f;
    }

    // Planar scatter bases (within one group buffer)
    int sbase[4];
    #pragma unroll
    for (int m = 0; m < 4; ++m) {
        int f    = 4 * t + m;
        int col  = f / 3;
        int chan = f - 3 * col;
        sbase[m] = chan * GPLANE + 8 + col;
    }

    const ulonglong2* xcol =
        reinterpret_cast<const ulonglong2*>(x4) + (size_t)n * (512 * ROWF4) + t;

    const int j = t & 127;               // output column
    const int c = t >> 7;                // channel plane
    float* opix0 = out + ((size_t)(n * 128 + i0) * 128 + j) * 3 + c;

    // ---- pipeline over 4 groups, ping-pong buffers ----
    phase1_group(xcol, 4 * i0 - 6, sm, sbase, w2, Wt, nullptr, 0, 0, nullptr);
    __syncthreads();

    #pragma unroll
    for (int g = 1; g < NGROUP; ++g) {
        float*       cur  = sm + (g & 1) * GBUF;
        const float* prev = sm + ((g - 1) & 1) * GBUF;
        phase1_group(xcol, 4 * (i0 + 4 * g) - 6, cur, sbase, w2, Wt,
                     prev, j, c, opix0 + (g - 1) * 4 * 384);
        __syncthreads();
    }

    // last group's horizontal pass (residual tail)
    #pragma unroll
    for (int rr = 0; rr < GROWS; ++rr)
        phase2_row(sm + ((NGROUP - 1) & 1) * GBUF, rr, j, c,
                   opix0 + (NGROUP - 1) * 4 * 384, Wt);
}

extern "C" void kernel_launch(void* const* d_in, const int* in_sizes, int n_in,
                              void* d_out, int out_size)
{
    (void)in_sizes; (void)n_in; (void)out_size;
    const float4* x4  = (const float4*)d_in[0];
    float*        out = (float*)d_out;

    cudaFuncSetAttribute(aa_fused, cudaFuncAttributeMaxDynamicSharedMemorySize, SMEM_BYTES);

    dim3 grid(8, 32);       // 8 row-tiles of 16 output rows x 32 images = 256 CTAs
    aa_fused<<<grid, 384, SMEM_BYTES>>>(x4, out);
}

// round 14
// speedup vs baseline: 1.0152x; 1.0152x over previous
#include <cuda_runtime.h>
#include <cuda_bf16.h>

// x: [32, 512, 512, 3] f32  -> out: [32, 128, 128, 3] f32
// 13-tap separable gaussian (sigma=1.5), zero padding, out = blur[4i, 4j]
//
// EXACT-FILL GRID: 296 CTAs (= 2/SM x 148 SMs, zero idle slots).
// Work = 1024 self-contained 4-row groups (32 images x 32 groups);
// CTAs 0..135 process 4 consecutive groups, CTAs 136..295 process 3
// (136*4 + 160*3 = 1024). CLC pairs (b, b+148) per SM -> 7 groups/SM
// (1.2% imbalance vs 13.5% at 256 CTAs).
// Per group: vertical scatter-accumulate stream (PF=6 ring, cache-policy
// segregated __ldcs/__ldg), planar smem, horizontal pass instruction-
// interleaved into the next group's vertical loop. __stcs outputs.

#define ROWF4   384              // float4 per input image row (512*3/4)
#define PROW    528              // floats per padded plane row (8 + 512 + 8)
#define GROWS   4                // output rows per group
#define GPLANE  (GROWS * PROW)   // floats per plane per group    = 2112
#define GBUF    (3 * GPLANE)     // floats per group buffer       = 6336
#define SMEM_BYTES (2 * GBUF * 4)   // 50688 B (ping-pong)

#define GNIN    (4 * GROWS + 9)  // input rows per group          = 25
#define PF      6                // ring depth; PF>=6 -> R0+s+PF >= 0 always

#define NCTA    296
#define NB4     136              // CTAs carrying 4 groups (rest carry 3)

__device__ __forceinline__ float4 f4zero() { return make_float4(0.f, 0.f, 0.f, 0.f); }

// one horizontal output row rr from a group buffer
__device__ __forceinline__ void phase2_row(
    const float* __restrict__ smbuf, int rr, int j, int c,
    float* __restrict__ opix, const float* __restrict__ Wt)
{
    const float4* sp4 = reinterpret_cast<const float4*>(smbuf)
                      + c * (GPLANE / 4) + rr * (PROW / 4) + j;
    float4 a = sp4[0];
    float4 b = sp4[1];
    float4 d = sp4[2];
    float4 e = sp4[3];
    // s[0..15] = cols 4j-8 .. 4j+7 ; taps at s[2..14]
    float acch;
    acch = Wt[0] * a.z;
    acch = fmaf(Wt[1],  a.w, acch);
    acch = fmaf(Wt[2],  b.x, acch);
    acch = fmaf(Wt[3],  b.y, acch);
    acch = fmaf(Wt[4],  b.z, acch);
    acch = fmaf(Wt[5],  b.w, acch);
    acch = fmaf(Wt[6],  d.x, acch);
    acch = fmaf(Wt[7],  d.y, acch);
    acch = fmaf(Wt[8],  d.z, acch);
    acch = fmaf(Wt[9],  d.w, acch);
    acch = fmaf(Wt[10], e.x, acch);
    acch = fmaf(Wt[11], e.y, acch);
    acch = fmaf(Wt[12], e.z, acch);
    __stcs(&opix[rr * 384], acch);           // streaming store (never re-read)
}

// vertical streaming pass for one 4-row group; if P2BUF != nullptr, one
// phase-2 row of the OTHER buffer is interleaved at s = 5, 11, 17, 23.
__device__ __forceinline__ void phase1_group(
    const float4* __restrict__ xcol, int R0,
    float* __restrict__ smbuf, const int* __restrict__ sbase,
    const float* __restrict__ Wt,
    const float* __restrict__ P2BUF, int j, int c, float* __restrict__ p2opix)
{
    float4 buf[PF];
    #pragma unroll
    for (int s = 0; s < PF; ++s) {               // preload rows R0 .. R0+5
        int r = R0 + s;                          // boundary rows: allocate in L2
        buf[s] = (r >= 0) ? __ldg(xcol + r * ROWF4) : f4zero();
    }

    float4 acc[GROWS];
    #pragma unroll
    for (int q = 0; q < GROWS; ++q) acc[q] = f4zero();

    #pragma unroll
    for (int s = 0; s < GNIN; ++s) {
        const float4 v = buf[s % PF];

        if (s + PF < GNIN) {                     // refill; R0+s+PF >= 0 (PF>=6)
            const int sr = s + PF;               // row index within group: 6..24
            int r = R0 + sr;
            if (r < 512) {
                if (sr >= GNIN - 9) {
                    buf[s % PF] = __ldg(xcol + r * ROWF4);   // re-read: allocate
                } else {
                    buf[s % PF] = __ldcs(xcol + r * ROWF4);  // read-once: evict-first
                }
            } else {
                buf[s % PF] = f4zero();
            }
        }

        const int p = s & 3;
        #pragma unroll
        for (int k = p; k <= 12; k += 4) {       // taps congruent to s mod 4
            const int ii = (s - k) >> 2;
            if (ii >= 0 && ii < GROWS) {
                const float wk = Wt[k];
                acc[ii].x = fmaf(wk, v.x, acc[ii].x);
                acc[ii].y = fmaf(wk, v.y, acc[ii].y);
                acc[ii].z = fmaf(wk, v.z, acc[ii].z);
                acc[ii].w = fmaf(wk, v.w, acc[ii].w);
            }
        }

        // output row ii completes at s = 4*ii + 12 -> flush (4x STS.32)
        if (s >= 12 && ((s - 12) & 3) == 0) {
            const int ii = (s - 12) >> 2;
            const int ro = ii * PROW;
            smbuf[sbase[0] + ro] = acc[ii].x;
            smbuf[sbase[1] + ro] = acc[ii].y;
            smbuf[sbase[2] + ro] = acc[ii].z;
            smbuf[sbase[3] + ro] = acc[ii].w;
        }

        // interleaved horizontal row of the previous group's buffer
        if (P2BUF != nullptr && (s == 5 || s == 11 || s == 17 || s == 23)) {
            phase2_row(P2BUF, (s - 5) / 6, j, c, p2opix, Wt);
        }
    }
}

__global__ __launch_bounds__(384, 2)
void aa_fused(const float4* __restrict__ x4, float* __restrict__ out)
{
    extern __shared__ float sm[];

    const int t = threadIdx.x;           // 0..383
    const int b = blockIdx.x;            // 0..295

    // group range for this CTA: 4 groups for b < NB4, else 3
    const int gstart = (b < NB4) ? 4 * b : 4 * NB4 + 3 * (b - NB4);
    const int gcnt   = (b < NB4) ? 4 : 3;

    // normalized 1-D gaussian (sigma = 1.5) as literals -> FFMA-imm
    const float Wt[13] = {
        0.00008922f, 0.00102822f, 0.00759740f, 0.03599436f,
        0.10934121f, 0.21296756f, 0.26596430f, 0.21296756f,
        0.10934121f, 0.03599436f, 0.00759740f, 0.00102822f,
        0.00008922f
    };

    // Zero horizontal padding of BOTH buffers:
    // 2 bufs * 3 planes * 4 rows * 16 pad floats = 384 = blockDim
    {
        int bufi  = t / 192;             // 0..1
        int rem   = t - bufi * 192;      // 0..191
        int plane = rem >> 6;            // 0..2
        int rem2  = rem & 63;
        int row   = rem2 >> 4;           // 0..3
        int o     = rem2 & 15;           // 0..15
        sm[bufi * GBUF + plane * GPLANE + row * PROW + (o < 8 ? o : 512 + o)] = 0.f;
    }

    // Planar scatter bases (within one group buffer)
    int sbase[4];
    #pragma unroll
    for (int m = 0; m < 4; ++m) {
        int f    = 4 * t + m;
        int col  = f / 3;
        int chan = f - 3 * col;
        sbase[m] = chan * GPLANE + 8 + col;
    }

    const int j = t & 127;               // output column
    const int c = t >> 7;                // channel plane

    float* prev_opix = nullptr;          // output base of previous group

    #pragma unroll 1
    for (int q = 0; q < gcnt; ++q) {
        const int g   = gstart + q;      // global group id
        const int n   = g >> 5;          // image (32 groups per image)
        const int i0g = (g & 31) * 4;    // first output row within image

        const float4* xcol = x4 + (size_t)n * (512 * ROWF4) + t;
        float* opix = out + ((size_t)(n * 128 + i0g) * 128 + j) * 3 + c;

        float*       cur  = sm + (q & 1) * GBUF;
        const float* prev = (q > 0) ? sm + ((q - 1) & 1) * GBUF : nullptr;

        phase1_group(xcol, 4 * i0g - 6, cur, sbase, Wt,
                     prev, j, c, prev_opix);
        __syncthreads();

        prev_opix = opix;
    }

    // last group's horizontal pass (residual tail)
    {
        const float* last = sm + ((gcnt - 1) & 1) * GBUF;
        #pragma unroll
        for (int rr = 0; rr < GROWS; ++rr)
            phase2_row(last, rr, j, c, prev_opix, Wt);
    }
}

extern "C" void kernel_launch(void* const* d_in, const int* in_sizes, int n_in,
                              void* d_out, int out_size)
{
    (void)in_sizes; (void)n_in; (void)out_size;
    const float4* x4  = (const float4*)d_in[0];
    float*        out = (float*)d_out;

    cudaFuncSetAttribute(aa_fused, cudaFuncAttributeMaxDynamicSharedMemorySize, SMEM_BYTES);

    aa_fused<<<NCTA, 384, SMEM_BYTES>>>(x4, out);   // 296 = 2/SM x 148, exact fill
}